// round 14
// baseline (speedup 1.0000x reference)
#include <cuda_runtime.h>
#include <cstdint>

// mean_aggregator: out[b,:] = (1/32) * sum_s emb[neighbors[b,s], :]
// B=50000, S=32, D=128, emb 500000x128 fp32 (256 MB > 126 MB L2).
//
// Persistent one-wave kernel, position-windowed sorted gather (R7/R11 proven
// config: 4 windows x 8 positions, inline r-outer/p-inner gather loops).
// R12 delta (ONE LINE): drop the fence after window 2 — windows 2,3 run
// back-to-back, saving one full-grid convergence tail. Fences remain after
// w0 and w1. Everything else byte-identical to the 82.1/82.4 us baseline.
//
// NOTE: gather loops are INLINE in the kernel body with a runtime window
// loop — refactoring them into a templated helper (R8-R10) changed ptxas
// load batching and cost ~35 us at identical DRAM bytes. Do not refactor.

#define THREADS 256
#define WPB (THREADS / 32)
#define ROWS 11
#define NW 4                       // 4 windows x 8 positions
#define POS_PER_W (32 / NW)
#define SPIN_LIMIT (1u << 17)

__device__ unsigned g_bar[NW];     // fence counters + exit counter

__device__ __forceinline__ void grid_fence(int b, int nblocks)
{
    __syncthreads();
    if (threadIdx.x == 0) {
        const unsigned old = atomicAdd(&g_bar[b], 1u);
        if (old == (unsigned)(nblocks - 1) && b > 0)
            g_bar[b - 1] = 0;                  // all blocks passed fence b-1
        unsigned tries = 0;
        while (*(volatile unsigned*)&g_bar[b] < (unsigned)nblocks &&
               tries < SPIN_LIMIT) {
            ++tries;
            __nanosleep(64);
        }
    }
    __syncthreads();
}

__global__ __launch_bounds__(THREADS, 4)
void mean_agg_poswin(const int* __restrict__ neighbors,
                     const float4* __restrict__ emb,   // [N, 32] float4
                     float4* __restrict__ out,         // [B, 32] float4
                     int batch)
{
    __shared__ int s_ids[WPB][ROWS][32];

    const int wid  = threadIdx.x >> 5;
    const int lane = threadIdx.x & 31;
    const int nblocks = gridDim.x;
    const int W   = nblocks * WPB;
    const int gw  = blockIdx.x * WPB + wid;

    // ---- load + warp-bitonic sort each owned row's 32 ids ----
    #pragma unroll
    for (int r = 0; r < ROWS; ++r) {
        const int row = gw + r * W;
        // Sentinel id 0 for inactive rows: harmless extra loads, result unused.
        int v = (row < batch) ? neighbors[row * 32 + lane] : 0;

        #pragma unroll
        for (int k = 2; k <= 32; k <<= 1) {
            #pragma unroll
            for (int j = k >> 1; j > 0; j >>= 1) {
                const int other  = __shfl_xor_sync(0xffffffffu, v, j);
                const bool up    = ((lane & k) == 0);
                const bool lower = ((lane & j) == 0);
                v = ((lower == up) ? min(v, other) : max(v, other));
            }
        }
        s_ids[wid][r][lane] = v;
    }
    __syncthreads();

    float4 acc[ROWS];
    #pragma unroll
    for (int r = 0; r < ROWS; ++r)
        acc[r] = make_float4(0.f, 0.f, 0.f, 0.f);

    // ---- position-windowed gather: static, fully unrolled ----
    for (int w = 0; w < NW; ++w) {
        const int base = w * POS_PER_W;
        #pragma unroll
        for (int r = 0; r < ROWS; ++r) {
            #pragma unroll
            for (int p = 0; p < POS_PER_W; ++p) {
                const int n = s_ids[wid][r][base + p];     // LDS broadcast
                const float4 v = __ldg(&emb[(size_t)n * 32 + lane]);
                acc[r].x += v.x;
                acc[r].y += v.y;
                acc[r].z += v.z;
                acc[r].w += v.w;
            }
        }
        if (w < NW - 2) grid_fence(w, nblocks);   // R12: no fence after w2
    }

    // ---- write means ----
    const float inv = 1.0f / 32.0f;
    #pragma unroll
    for (int r = 0; r < ROWS; ++r) {
        const int row = gw + r * W;
        if (row < batch) {
            float4 a = acc[r];
            a.x *= inv; a.y *= inv; a.z *= inv; a.w *= inv;
            out[(size_t)row * 32 + lane] = a;
        }
    }

    // ---- exit: reset fence state for next graph replay ----
    __syncthreads();
    if (threadIdx.x == 0) {
        const unsigned old = atomicAdd(&g_bar[NW - 1], 1u);
        if (old == (unsigned)(nblocks - 1)) {
            g_bar[NW - 3] = 0;     // fence 0 counter
            g_bar[NW - 2] = 0;     // fence 1 counter
            g_bar[NW - 1] = 0;     // exit counter
        }
    }
}

// Fallback (R1 kernel) for shapes exceeding persistent capacity.
__global__ __launch_bounds__(THREADS)
void mean_agg_naive(const int* __restrict__ neighbors,
                    const float4* __restrict__ emb,
                    float4* __restrict__ out, int batch)
{
    const int warp = (blockIdx.x * blockDim.x + threadIdx.x) >> 5;
    const int lane = threadIdx.x & 31;
    if (warp >= batch) return;
    const int my = neighbors[warp * 32 + lane];
    float4 acc = make_float4(0.f, 0.f, 0.f, 0.f);
    #pragma unroll
    for (int s = 0; s < 32; ++s) {
        const int n = __shfl_sync(0xffffffffu, my, s);
        const float4 v = __ldg(&emb[(size_t)n * 32 + lane]);
        acc.x += v.x; acc.y += v.y; acc.z += v.z; acc.w += v.w;
    }
    const float inv = 1.0f / 32.0f;
    acc.x *= inv; acc.y *= inv; acc.z *= inv; acc.w *= inv;
    out[(size_t)warp * 32 + lane] = acc;
}

extern "C" void kernel_launch(void* const* d_in, const int* in_sizes, int n_in,
                              void* d_out, int out_size)
{
    const int* neighbors = (const int*)d_in[0];     // [B, 32] int32
    const float4* emb    = (const float4*)d_in[1];  // [N, 128] fp32 as float4

    const int batch = in_sizes[0] / 32;             // 50000

    int sms = 0;
    if (cudaDeviceGetAttribute(&sms, cudaDevAttrMultiProcessorCount, 0) !=
            cudaSuccess || sms <= 0)
        sms = 148;

    const int nblocks = sms * 4;                    // one guaranteed wave
    const long long capacity = (long long)nblocks * WPB * ROWS;

    if ((long long)batch <= capacity) {
        mean_agg_poswin<<<nblocks, THREADS>>>(neighbors, emb,
                                              (float4*)d_out, batch);
    } else {
        const int blocks = (batch + WPB - 1) / WPB;
        mean_agg_naive<<<blocks, THREADS>>>(neighbors, emb,
                                            (float4*)d_out, batch);
    }
}

// round 15
// speedup vs baseline: 1.0968x; 1.0968x over previous
#include <cuda_runtime.h>
#include <cstdint>

// mean_aggregator: out[b,:] = (1/32) * sum_s emb[neighbors[b,s], :]
// B=50000, S=32, D=128, emb 500000x128 fp32 (256 MB > 126 MB L2).
//
// FINAL (R7/R11 config, reproduced at 82.1 / 82.4 us):
// Persistent one-wave kernel, position-windowed sorted gather:
//  - each warp owns ROWS rows; ids warp-bitonic sorted into smem once
//  - float4 accumulators live in registers for the whole kernel
//  - window w gathers sorted POSITIONS [8w, 8w+8): static trip count ->
//    fully unrolled independent loads (8-load batches fit the 64-reg budget)
//  - sorted order makes position ~ value (order statistics); soft grid fences
//    between ALL windows keep resident warps in the same ~64-100 MB value
//    region -> L2-resident window, each table row ~one DRAM fetch.
//  - fences are pure locality hints: correctness never depends on them.
//
// Measured wall: L2->SM service of the 850 MB gather stream at ~94% of the
// LTS cap. DO NOT: refactor gather loops into helpers (R8-R10: -35 us at
// equal bytes), remove the last fence (R12: -8 us at equal bytes).

#define THREADS 256
#define WPB (THREADS / 32)
#define ROWS 11
#define NW 4                       // 4 windows x 8 positions
#define POS_PER_W (32 / NW)
#define SPIN_LIMIT (1u << 17)

__device__ unsigned g_bar[NW];     // NW-1 fence counters + 1 exit counter

__device__ __forceinline__ void grid_fence(int b, int nblocks)
{
    __syncthreads();
    if (threadIdx.x == 0) {
        const unsigned old = atomicAdd(&g_bar[b], 1u);
        if (old == (unsigned)(nblocks - 1) && b > 0)
            g_bar[b - 1] = 0;                  // all blocks passed fence b-1
        unsigned tries = 0;
        while (*(volatile unsigned*)&g_bar[b] < (unsigned)nblocks &&
               tries < SPIN_LIMIT) {
            ++tries;
            __nanosleep(64);
        }
    }
    __syncthreads();
}

__global__ __launch_bounds__(THREADS, 4)
void mean_agg_poswin(const int* __restrict__ neighbors,
                     const float4* __restrict__ emb,   // [N, 32] float4
                     float4* __restrict__ out,         // [B, 32] float4
                     int batch)
{
    __shared__ int s_ids[WPB][ROWS][32];

    const int wid  = threadIdx.x >> 5;
    const int lane = threadIdx.x & 31;
    const int nblocks = gridDim.x;
    const int W   = nblocks * WPB;
    const int gw  = blockIdx.x * WPB + wid;

    // ---- load + warp-bitonic sort each owned row's 32 ids ----
    #pragma unroll
    for (int r = 0; r < ROWS; ++r) {
        const int row = gw + r * W;
        // Sentinel id 0 for inactive rows: harmless extra loads, result unused.
        int v = (row < batch) ? neighbors[row * 32 + lane] : 0;

        #pragma unroll
        for (int k = 2; k <= 32; k <<= 1) {
            #pragma unroll
            for (int j = k >> 1; j > 0; j >>= 1) {
                const int other  = __shfl_xor_sync(0xffffffffu, v, j);
                const bool up    = ((lane & k) == 0);
                const bool lower = ((lane & j) == 0);
                v = ((lower == up) ? min(v, other) : max(v, other));
            }
        }
        s_ids[wid][r][lane] = v;
    }
    __syncthreads();

    float4 acc[ROWS];
    #pragma unroll
    for (int r = 0; r < ROWS; ++r)
        acc[r] = make_float4(0.f, 0.f, 0.f, 0.f);

    // ---- position-windowed gather: static, fully unrolled ----
    for (int w = 0; w < NW; ++w) {
        const int base = w * POS_PER_W;
        #pragma unroll
        for (int r = 0; r < ROWS; ++r) {
            #pragma unroll
            for (int p = 0; p < POS_PER_W; ++p) {
                const int n = s_ids[wid][r][base + p];     // LDS broadcast
                const float4 v = __ldg(&emb[(size_t)n * 32 + lane]);
                acc[r].x += v.x;
                acc[r].y += v.y;
                acc[r].z += v.z;
                acc[r].w += v.w;
            }
        }
        if (w < NW - 1) grid_fence(w, nblocks);
    }

    // ---- write means ----
    const float inv = 1.0f / 32.0f;
    #pragma unroll
    for (int r = 0; r < ROWS; ++r) {
        const int row = gw + r * W;
        if (row < batch) {
            float4 a = acc[r];
            a.x *= inv; a.y *= inv; a.z *= inv; a.w *= inv;
            out[(size_t)row * 32 + lane] = a;
        }
    }

    // ---- exit: reset fence state for next graph replay ----
    __syncthreads();
    if (threadIdx.x == 0) {
        const unsigned old = atomicAdd(&g_bar[NW - 1], 1u);
        if (old == (unsigned)(nblocks - 1)) {
            g_bar[NW - 2] = 0;
            g_bar[NW - 1] = 0;
        }
    }
}

// Fallback (R1 kernel) for shapes exceeding persistent capacity.
__global__ __launch_bounds__(THREADS)
void mean_agg_naive(const int* __restrict__ neighbors,
                    const float4* __restrict__ emb,
                    float4* __restrict__ out, int batch)
{
    const int warp = (blockIdx.x * blockDim.x + threadIdx.x) >> 5;
    const int lane = threadIdx.x & 31;
    if (warp >= batch) return;
    const int my = neighbors[warp * 32 + lane];
    float4 acc = make_float4(0.f, 0.f, 0.f, 0.f);
    #pragma unroll
    for (int s = 0; s < 32; ++s) {
        const int n = __shfl_sync(0xffffffffu, my, s);
        const float4 v = __ldg(&emb[(size_t)n * 32 + lane]);
        acc.x += v.x; acc.y += v.y; acc.z += v.z; acc.w += v.w;
    }
    const float inv = 1.0f / 32.0f;
    acc.x *= inv; acc.y *= inv; acc.z *= inv; acc.w *= inv;
    out[(size_t)warp * 32 + lane] = acc;
}

extern "C" void kernel_launch(void* const* d_in, const int* in_sizes, int n_in,
                              void* d_out, int out_size)
{
    const int* neighbors = (const int*)d_in[0];     // [B, 32] int32
    const float4* emb    = (const float4*)d_in[1];  // [N, 128] fp32 as float4

    const int batch = in_sizes[0] / 32;             // 50000

    int sms = 0;
    if (cudaDeviceGetAttribute(&sms, cudaDevAttrMultiProcessorCount, 0) !=
            cudaSuccess || sms <= 0)
        sms = 148;

    const int nblocks = sms * 4;                    // one guaranteed wave
    const long long capacity = (long long)nblocks * WPB * ROWS;

    if ((long long)batch <= capacity) {
        mean_agg_poswin<<<nblocks, THREADS>>>(neighbors, emb,
                                              (float4*)d_out, batch);
    } else {
        const int blocks = (batch + WPB - 1) / WPB;
        mean_agg_naive<<<blocks, THREADS>>>(neighbors, emb,
                                            (float4*)d_out, batch);
    }
}